// round 1
// baseline (speedup 1.0000x reference)
#include <cuda_runtime.h>
#include <cuda_bf16.h>
#include <math.h>

// ---------------------------------------------------------------------------
// TransformerBlock: x[1,256,64,64] -> same shape.
// N = 4096 tokens, C = 256 channels, 8 heads, d = 32.
// Scratch in __device__ globals (no allocation allowed).
// ---------------------------------------------------------------------------

#define NTOK 4096
#define CDIM 256
#define HEADS 8
#define HDIM 32

__device__ float g_xl[NTOK * CDIM];        // residual stream, channels-last
__device__ float g_xn[NTOK * CDIM];        // LN output
__device__ float g_qkv[NTOK * 3 * CDIM];   // [n][3*256]
__device__ float g_att[NTOK * CDIM];       // attention output [n][c]
__device__ float g_h1[NTOK * 4 * CDIM];    // MLP hidden [n][1024]

// ---------------------------------------------------------------------------
// Tiled transpose: dst[c][r] = src[r][c], src is [R, C] row-major.
// ---------------------------------------------------------------------------
__global__ void transpose_k(const float* __restrict__ src, float* __restrict__ dst,
                            int R, int C) {
    __shared__ float tile[32][33];
    int c0 = blockIdx.x * 32, r0 = blockIdx.y * 32;
    int x = threadIdx.x, y = threadIdx.y;
#pragma unroll
    for (int i = y; i < 32; i += 8)
        tile[i][x] = src[(size_t)(r0 + i) * C + c0 + x];
    __syncthreads();
#pragma unroll
    for (int i = y; i < 32; i += 8)
        dst[(size_t)(c0 + i) * R + r0 + x] = tile[x][i];
}

// ---------------------------------------------------------------------------
// LayerNorm over rows of [NTOK, 256]. One block per token, 256 threads.
// ---------------------------------------------------------------------------
__global__ void ln_kernel(const float* __restrict__ in, const float* __restrict__ g,
                          const float* __restrict__ b, float* __restrict__ out) {
    int n = blockIdx.x;
    int c = threadIdx.x;
    float v = in[n * CDIM + c];
    float s1 = v, s2 = v * v;
#pragma unroll
    for (int off = 16; off > 0; off >>= 1) {
        s1 += __shfl_xor_sync(0xFFFFFFFFu, s1, off);
        s2 += __shfl_xor_sync(0xFFFFFFFFu, s2, off);
    }
    __shared__ float sh1[8], sh2[8];
    int w = c >> 5, lane = c & 31;
    if (lane == 0) { sh1[w] = s1; sh2[w] = s2; }
    __syncthreads();
    float m1 = 0.f, m2 = 0.f;
#pragma unroll
    for (int i = 0; i < 8; i++) { m1 += sh1[i]; m2 += sh2[i]; }
    float mu = m1 * (1.f / CDIM);
    float var = m2 * (1.f / CDIM) - mu * mu;
    float rs = rsqrtf(var + 1e-5f);
    out[n * CDIM + c] = (v - mu) * rs * g[c] + b[c];
}

// ---------------------------------------------------------------------------
// SGEMM: C[M,N] = A[M,K] * B[N,K]^T + bias[N], optional epilogue.
// EPI: 0 = plain, 1 = exact GELU, 2 = += residual (res may alias C).
// BM = BN = 64, BK = 16, 256 threads, 4x4 per thread.
// M % 64 == 0, N % 64 == 0, K % 16 == 0 assumed.
// ---------------------------------------------------------------------------
template <int EPI>
__global__ __launch_bounds__(256)
void sgemm_tn(const float* __restrict__ A, const float* __restrict__ B,
              const float* __restrict__ bias, const float* __restrict__ res,
              float* __restrict__ C, int M, int N, int K) {
    __shared__ float As[16][64];
    __shared__ float Bs[16][64];
    int tid = threadIdx.x;
    int m0 = blockIdx.y * 64, n0 = blockIdx.x * 64;
    int lrow = tid >> 2, lseg = tid & 3;
    int tx = tid & 15, ty = tid >> 4;
    float acc[4][4] = {};

    for (int k0 = 0; k0 < K; k0 += 16) {
        float4 av = *(const float4*)(A + (size_t)(m0 + lrow) * K + k0 + lseg * 4);
        float4 bv = *(const float4*)(B + (size_t)(n0 + lrow) * K + k0 + lseg * 4);
        __syncthreads();
        As[lseg * 4 + 0][lrow] = av.x; As[lseg * 4 + 1][lrow] = av.y;
        As[lseg * 4 + 2][lrow] = av.z; As[lseg * 4 + 3][lrow] = av.w;
        Bs[lseg * 4 + 0][lrow] = bv.x; Bs[lseg * 4 + 1][lrow] = bv.y;
        Bs[lseg * 4 + 2][lrow] = bv.z; Bs[lseg * 4 + 3][lrow] = bv.w;
        __syncthreads();
#pragma unroll
        for (int kk = 0; kk < 16; kk++) {
            float4 a4 = *(const float4*)&As[kk][ty * 4];
            float4 b4 = *(const float4*)&Bs[kk][tx * 4];
            float aa[4] = {a4.x, a4.y, a4.z, a4.w};
            float bb[4] = {b4.x, b4.y, b4.z, b4.w};
#pragma unroll
            for (int i = 0; i < 4; i++)
#pragma unroll
                for (int j = 0; j < 4; j++)
                    acc[i][j] = fmaf(aa[i], bb[j], acc[i][j]);
        }
    }

#pragma unroll
    for (int i = 0; i < 4; i++) {
        int row = m0 + ty * 4 + i;
#pragma unroll
        for (int j = 0; j < 4; j++) {
            int col = n0 + tx * 4 + j;
            float v = acc[i][j] + bias[col];
            if (EPI == 1) v = 0.5f * v * (1.0f + erff(v * 0.70710678118654752f));
            if (EPI == 2) v += res[(size_t)row * N + col];
            C[(size_t)row * N + col] = v;
        }
    }
}

// ---------------------------------------------------------------------------
// Fast exp2 for y <= 0 (FMA-pipe, avoids MUFU throughput wall).
// Degree-6 Taylor of 2^f on f in [-0.5, 0.5], rel err ~1.2e-7.
// ---------------------------------------------------------------------------
__device__ __forceinline__ float exp2_fast(float y) {
    y = fmaxf(y, -126.0f);
    int ni = __float2int_rn(y);
    float f = y - (float)ni;
    float p = 1.5403530e-4f;
    p = fmaf(p, f, 1.33335581e-3f);
    p = fmaf(p, f, 9.61812911e-3f);
    p = fmaf(p, f, 5.55041087e-2f);
    p = fmaf(p, f, 2.40226507e-1f);
    p = fmaf(p, f, 6.93147181e-1f);
    p = fmaf(p, f, 1.0f);
    float sc = __int_as_float((ni + 127) << 23);
    return p * sc;
}

// ---------------------------------------------------------------------------
// Flash-style attention. One thread per query row; block = 128 queries.
// grid = (NTOK/128, HEADS). K/V tiles of 32 keys staged in SMEM.
// qkv layout: [n][768], q at +0, k at +256, v at +512; head h at +h*32.
// Scale (1/sqrt(32)) and log2(e) folded into q.
// ---------------------------------------------------------------------------
__global__ __launch_bounds__(128)
void attn_kernel(const float* __restrict__ qkv, float* __restrict__ att) {
    const int h = blockIdx.y;
    const int n = blockIdx.x * 128 + threadIdx.x;

    __shared__ float ks[32][32];
    __shared__ float vs[32][32];

    // scale * log2(e) so softmax exponentials become exp2 of (s - m)
    const float qscale = 0.17677669529663687f * 1.4426950408889634f;

    float q[HDIM], o[HDIM];
    const float* qp = qkv + (size_t)n * 768 + h * HDIM;
#pragma unroll
    for (int dd = 0; dd < HDIM; dd++) { q[dd] = qp[dd] * qscale; o[dd] = 0.f; }
    float m = -1e30f, l = 0.f;

    const int t = threadIdx.x;
    for (int kt = 0; kt < NTOK / 32; kt++) {
        __syncthreads();
        // load 32x32 K and V tiles (256 float4 each, 128 threads -> 2 apiece)
#pragma unroll
        for (int r = 0; r < 2; r++) {
            int idx = t + r * 128;        // 0..255
            int row = idx >> 3;           // 0..31
            int seg = idx & 7;            // 0..7
            const float* base = qkv + (size_t)(kt * 32 + row) * 768 + h * HDIM;
            float4 k4 = *(const float4*)(base + 256 + seg * 4);
            float4 v4 = *(const float4*)(base + 512 + seg * 4);
            *(float4*)&ks[row][seg * 4] = k4;
            *(float4*)&vs[row][seg * 4] = v4;
        }
        __syncthreads();

        float s[32];
        float mt = m;
#pragma unroll 8
        for (int j = 0; j < 32; j++) {
            float s0 = 0.f, s1 = 0.f;
#pragma unroll
            for (int dd = 0; dd < HDIM; dd += 2) {
                s0 = fmaf(q[dd],     ks[j][dd],     s0);
                s1 = fmaf(q[dd + 1], ks[j][dd + 1], s1);
            }
            s[j] = s0 + s1;
            mt = fmaxf(mt, s[j]);
        }

        float corr = exp2_fast(m - mt);
        l *= corr;
#pragma unroll
        for (int dd = 0; dd < HDIM; dd++) o[dd] *= corr;

#pragma unroll 8
        for (int j = 0; j < 32; j++) {
            float p = exp2_fast(s[j] - mt);
            l += p;
#pragma unroll
            for (int dd = 0; dd < HDIM; dd++)
                o[dd] = fmaf(p, vs[j][dd], o[dd]);
        }
        m = mt;
    }

    float inv = 1.0f / l;
    float* op = att + (size_t)n * CDIM + h * HDIM;
#pragma unroll
    for (int dd = 0; dd < HDIM; dd += 4) {
        float4 v4 = make_float4(o[dd] * inv, o[dd + 1] * inv,
                                o[dd + 2] * inv, o[dd + 3] * inv);
        *(float4*)(op + dd) = v4;
    }
}

// ---------------------------------------------------------------------------
// Launch
// ---------------------------------------------------------------------------
extern "C" void kernel_launch(void* const* d_in, const int* in_sizes, int n_in,
                              void* d_out, int out_size) {
    const float* x      = (const float*)d_in[0];   // [1,256,64,64]
    const float* ln1_g  = (const float*)d_in[1];
    const float* ln1_b  = (const float*)d_in[2];
    const float* w_qkv  = (const float*)d_in[3];   // [768,256]
    const float* b_qkv  = (const float*)d_in[4];
    const float* w_proj = (const float*)d_in[5];   // [256,256]
    const float* b_proj = (const float*)d_in[6];
    const float* ln2_g  = (const float*)d_in[7];
    const float* ln2_b  = (const float*)d_in[8];
    const float* w_mlp1 = (const float*)d_in[9];   // [1024,256]
    const float* b_mlp1 = (const float*)d_in[10];
    const float* w_mlp2 = (const float*)d_in[11];  // [256,1024]
    const float* b_mlp2 = (const float*)d_in[12];
    float* out = (float*)d_out;

    float *xl, *xn, *qkv, *att, *h1;
    cudaGetSymbolAddress((void**)&xl,  g_xl);
    cudaGetSymbolAddress((void**)&xn,  g_xn);
    cudaGetSymbolAddress((void**)&qkv, g_qkv);
    cudaGetSymbolAddress((void**)&att, g_att);
    cudaGetSymbolAddress((void**)&h1,  g_h1);

    dim3 tb(32, 8);

    // x[256,4096] -> xl[4096,256]
    transpose_k<<<dim3(NTOK / 32, CDIM / 32), tb>>>(x, xl, CDIM, NTOK);

    // LN1
    ln_kernel<<<NTOK, CDIM>>>(xl, ln1_g, ln1_b, xn);

    // QKV: [4096,768]
    sgemm_tn<0><<<dim3(768 / 64, NTOK / 64), 256>>>(xn, w_qkv, b_qkv, nullptr,
                                                    qkv, NTOK, 768, CDIM);

    // Attention
    attn_kernel<<<dim3(NTOK / 128, HEADS), 128>>>(qkv, att);

    // proj + residual: xl = xl + att @ w_proj^T + b
    sgemm_tn<2><<<dim3(CDIM / 64, NTOK / 64), 256>>>(att, w_proj, b_proj, xl,
                                                     xl, NTOK, CDIM, CDIM);

    // LN2
    ln_kernel<<<NTOK, CDIM>>>(xl, ln2_g, ln2_b, xn);

    // MLP1 + GELU: h1[4096,1024]
    sgemm_tn<1><<<dim3(1024 / 64, NTOK / 64), 256>>>(xn, w_mlp1, b_mlp1, nullptr,
                                                     h1, NTOK, 1024, CDIM);

    // MLP2 + residual: xl = xl + h1 @ w_mlp2^T + b
    sgemm_tn<2><<<dim3(CDIM / 64, NTOK / 64), 256>>>(h1, w_mlp2, b_mlp2, xl,
                                                     xl, NTOK, CDIM, 4 * CDIM);

    // xl[4096,256] -> out[256,4096]
    transpose_k<<<dim3(CDIM / 32, NTOK / 32), tb>>>(xl, out, NTOK, CDIM);
}

// round 2
// speedup vs baseline: 1.1586x; 1.1586x over previous
#include <cuda_runtime.h>
#include <cuda_bf16.h>
#include <math.h>

// ---------------------------------------------------------------------------
// TransformerBlock: x[1,256,64,64] -> same shape.
// N = 4096 tokens, C = 256 channels, 8 heads, d = 32.
// ---------------------------------------------------------------------------

#define NTOK 4096
#define CDIM 256
#define HEADS 8
#define HDIM 32
#define NCHUNK 4
#define CHUNK (NTOK / NCHUNK)

__device__ float g_xl[NTOK * CDIM];
__device__ float g_xn[NTOK * CDIM];
__device__ float g_qkv[NTOK * 3 * CDIM];
__device__ float g_att[NTOK * CDIM];
__device__ float g_h1[NTOK * 4 * CDIM];
// split-KV partials
__device__ float g_po[NCHUNK * HEADS * NTOK * HDIM];
__device__ float g_pm[NCHUNK * HEADS * NTOK];
__device__ float g_pl[NCHUNK * HEADS * NTOK];

// ---------------------------------------------------------------------------
__global__ void transpose_k(const float* __restrict__ src, float* __restrict__ dst,
                            int R, int C) {
    __shared__ float tile[32][33];
    int c0 = blockIdx.x * 32, r0 = blockIdx.y * 32;
    int x = threadIdx.x, y = threadIdx.y;
#pragma unroll
    for (int i = y; i < 32; i += 8)
        tile[i][x] = src[(size_t)(r0 + i) * C + c0 + x];
    __syncthreads();
#pragma unroll
    for (int i = y; i < 32; i += 8)
        dst[(size_t)(c0 + i) * R + r0 + x] = tile[x][i];
}

// ---------------------------------------------------------------------------
__global__ void ln_kernel(const float* __restrict__ in, const float* __restrict__ g,
                          const float* __restrict__ b, float* __restrict__ out) {
    int n = blockIdx.x;
    int c = threadIdx.x;
    float v = in[n * CDIM + c];
    float s1 = v, s2 = v * v;
#pragma unroll
    for (int off = 16; off > 0; off >>= 1) {
        s1 += __shfl_xor_sync(0xFFFFFFFFu, s1, off);
        s2 += __shfl_xor_sync(0xFFFFFFFFu, s2, off);
    }
    __shared__ float sh1[8], sh2[8];
    int w = c >> 5, lane = c & 31;
    if (lane == 0) { sh1[w] = s1; sh2[w] = s2; }
    __syncthreads();
    float m1 = 0.f, m2 = 0.f;
#pragma unroll
    for (int i = 0; i < 8; i++) { m1 += sh1[i]; m2 += sh2[i]; }
    float mu = m1 * (1.f / CDIM);
    float var = m2 * (1.f / CDIM) - mu * mu;
    float rs = rsqrtf(var + 1e-5f);
    out[n * CDIM + c] = (v - mu) * rs * g[c] + b[c];
}

// ---------------------------------------------------------------------------
// SGEMM: C[M,N] = A[M,K] * B[N,K]^T + bias[N].  EPI: 0 plain, 1 GELU, 2 +res.
// ---------------------------------------------------------------------------
template <int EPI>
__global__ __launch_bounds__(256)
void sgemm_tn(const float* __restrict__ A, const float* __restrict__ B,
              const float* __restrict__ bias, const float* __restrict__ res,
              float* __restrict__ C, int M, int N, int K) {
    __shared__ float As[16][64];
    __shared__ float Bs[16][64];
    int tid = threadIdx.x;
    int m0 = blockIdx.y * 64, n0 = blockIdx.x * 64;
    int lrow = tid >> 2, lseg = tid & 3;
    int tx = tid & 15, ty = tid >> 4;
    float acc[4][4] = {};

    for (int k0 = 0; k0 < K; k0 += 16) {
        float4 av = *(const float4*)(A + (size_t)(m0 + lrow) * K + k0 + lseg * 4);
        float4 bv = *(const float4*)(B + (size_t)(n0 + lrow) * K + k0 + lseg * 4);
        __syncthreads();
        As[lseg * 4 + 0][lrow] = av.x; As[lseg * 4 + 1][lrow] = av.y;
        As[lseg * 4 + 2][lrow] = av.z; As[lseg * 4 + 3][lrow] = av.w;
        Bs[lseg * 4 + 0][lrow] = bv.x; Bs[lseg * 4 + 1][lrow] = bv.y;
        Bs[lseg * 4 + 2][lrow] = bv.z; Bs[lseg * 4 + 3][lrow] = bv.w;
        __syncthreads();
#pragma unroll
        for (int kk = 0; kk < 16; kk++) {
            float4 a4 = *(const float4*)&As[kk][ty * 4];
            float4 b4 = *(const float4*)&Bs[kk][tx * 4];
            float aa[4] = {a4.x, a4.y, a4.z, a4.w};
            float bb[4] = {b4.x, b4.y, b4.z, b4.w};
#pragma unroll
            for (int i = 0; i < 4; i++)
#pragma unroll
                for (int j = 0; j < 4; j++)
                    acc[i][j] = fmaf(aa[i], bb[j], acc[i][j]);
        }
    }

#pragma unroll
    for (int i = 0; i < 4; i++) {
        int row = m0 + ty * 4 + i;
#pragma unroll
        for (int j = 0; j < 4; j++) {
            int col = n0 + tx * 4 + j;
            float v = acc[i][j] + bias[col];
            if (EPI == 1) v = 0.5f * v * (1.0f + erff(v * 0.70710678118654752f));
            if (EPI == 2) v += res[(size_t)row * N + col];
            C[(size_t)row * N + col] = v;
        }
    }
}

// ---------------------------------------------------------------------------
// Fast exp2 (FMA pipe). Valid for y <= ~0, rel err ~1e-7.
// ---------------------------------------------------------------------------
__device__ __forceinline__ float exp2_fast(float y) {
    y = fmaxf(y, -126.0f);
    int ni = __float2int_rn(y);
    float f = y - (float)ni;
    float p = 1.5403530e-4f;
    p = fmaf(p, f, 1.33335581e-3f);
    p = fmaf(p, f, 9.61812911e-3f);
    p = fmaf(p, f, 5.55041087e-2f);
    p = fmaf(p, f, 2.40226507e-1f);
    p = fmaf(p, f, 6.93147181e-1f);
    p = fmaf(p, f, 1.0f);
    float sc = __int_as_float((ni + 127) << 23);
    return p * sc;
}

// ---------------------------------------------------------------------------
// Split-KV flash attention. grid = (NTOK/128, HEADS, NCHUNK).
// One thread per query; each block covers keys [z*CHUNK, (z+1)*CHUNK).
// All SMEM reads are float4 (LDS.128, uniform-address broadcast).
// Emits unnormalized partial (o, m, l).
// ---------------------------------------------------------------------------
__global__ __launch_bounds__(128)
void attn_kernel(const float* __restrict__ qkv,
                 float* __restrict__ po, float* __restrict__ pm,
                 float* __restrict__ pl) {
    const int h = blockIdx.y;
    const int z = blockIdx.z;
    const int n = blockIdx.x * 128 + threadIdx.x;

    __shared__ float ks[32][32];
    __shared__ float vs[32][32];

    const float qscale = 0.17677669529663687f * 1.4426950408889634f;

    float q[HDIM], o[HDIM];
    const float* qp = qkv + (size_t)n * 768 + h * HDIM;
#pragma unroll
    for (int dd = 0; dd < HDIM; dd++) { q[dd] = qp[dd] * qscale; o[dd] = 0.f; }
    float m = -1e30f, l = 0.f;

    const int t = threadIdx.x;
    const int key0 = z * CHUNK;
    for (int kt = 0; kt < CHUNK / 32; kt++) {
        __syncthreads();
#pragma unroll
        for (int r = 0; r < 2; r++) {
            int idx = t + r * 128;
            int row = idx >> 3;
            int seg = idx & 7;
            const float* base = qkv + (size_t)(key0 + kt * 32 + row) * 768 + h * HDIM;
            *(float4*)&ks[row][seg * 4] = *(const float4*)(base + 256 + seg * 4);
            *(float4*)&vs[row][seg * 4] = *(const float4*)(base + 512 + seg * 4);
        }
        __syncthreads();

        float s[32];
        float mt = m;
#pragma unroll 4
        for (int j = 0; j < 32; j++) {
            const float4* kp = (const float4*)&ks[j][0];
            float a0 = 0.f, a1 = 0.f, a2 = 0.f, a3 = 0.f;
#pragma unroll
            for (int w = 0; w < 8; w++) {
                float4 k4 = kp[w];
                a0 = fmaf(q[4 * w + 0], k4.x, a0);
                a1 = fmaf(q[4 * w + 1], k4.y, a1);
                a2 = fmaf(q[4 * w + 2], k4.z, a2);
                a3 = fmaf(q[4 * w + 3], k4.w, a3);
            }
            s[j] = (a0 + a1) + (a2 + a3);
            mt = fmaxf(mt, s[j]);
        }

        float corr = exp2_fast(m - mt);
        l *= corr;
#pragma unroll
        for (int dd = 0; dd < HDIM; dd++) o[dd] *= corr;

#pragma unroll 4
        for (int j = 0; j < 32; j++) {
            float p = exp2_fast(s[j] - mt);
            l += p;
            const float4* vp = (const float4*)&vs[j][0];
#pragma unroll
            for (int w = 0; w < 8; w++) {
                float4 v4 = vp[w];
                o[4 * w + 0] = fmaf(p, v4.x, o[4 * w + 0]);
                o[4 * w + 1] = fmaf(p, v4.y, o[4 * w + 1]);
                o[4 * w + 2] = fmaf(p, v4.z, o[4 * w + 2]);
                o[4 * w + 3] = fmaf(p, v4.w, o[4 * w + 3]);
            }
        }
        m = mt;
    }

    size_t ridx = ((size_t)z * HEADS + h) * NTOK + n;
    pm[ridx] = m;
    pl[ridx] = l;
    float* op = po + ridx * HDIM;
#pragma unroll
    for (int dd = 0; dd < HDIM; dd += 4)
        *(float4*)(op + dd) = make_float4(o[dd], o[dd + 1], o[dd + 2], o[dd + 3]);
}

// ---------------------------------------------------------------------------
// Combine split-KV partials. One warp per (head, token) row; lane = dim.
// ---------------------------------------------------------------------------
__global__ __launch_bounds__(256)
void attn_combine(const float* __restrict__ po, const float* __restrict__ pm,
                  const float* __restrict__ pl, float* __restrict__ att) {
    int row = blockIdx.x * 8 + (threadIdx.x >> 5);   // 0 .. HEADS*NTOK-1
    int lane = threadIdx.x & 31;
    int h = row / NTOK, n = row % NTOK;

    float mstar = -1e30f;
#pragma unroll
    for (int c = 0; c < NCHUNK; c++)
        mstar = fmaxf(mstar, pm[((size_t)c * HEADS + h) * NTOK + n]);

    float l = 0.f, o = 0.f;
#pragma unroll
    for (int c = 0; c < NCHUNK; c++) {
        size_t ridx = ((size_t)c * HEADS + h) * NTOK + n;
        float w = exp2_fast(pm[ridx] - mstar);
        l += pl[ridx] * w;
        o = fmaf(po[ridx * HDIM + lane], w, o);
    }
    att[(size_t)n * CDIM + h * HDIM + lane] = o / l;
}

// ---------------------------------------------------------------------------
extern "C" void kernel_launch(void* const* d_in, const int* in_sizes, int n_in,
                              void* d_out, int out_size) {
    const float* x      = (const float*)d_in[0];
    const float* ln1_g  = (const float*)d_in[1];
    const float* ln1_b  = (const float*)d_in[2];
    const float* w_qkv  = (const float*)d_in[3];
    const float* b_qkv  = (const float*)d_in[4];
    const float* w_proj = (const float*)d_in[5];
    const float* b_proj = (const float*)d_in[6];
    const float* ln2_g  = (const float*)d_in[7];
    const float* ln2_b  = (const float*)d_in[8];
    const float* w_mlp1 = (const float*)d_in[9];
    const float* b_mlp1 = (const float*)d_in[10];
    const float* w_mlp2 = (const float*)d_in[11];
    const float* b_mlp2 = (const float*)d_in[12];
    float* out = (float*)d_out;

    float *xl, *xn, *qkv, *att, *h1, *po, *pm, *pl;
    cudaGetSymbolAddress((void**)&xl,  g_xl);
    cudaGetSymbolAddress((void**)&xn,  g_xn);
    cudaGetSymbolAddress((void**)&qkv, g_qkv);
    cudaGetSymbolAddress((void**)&att, g_att);
    cudaGetSymbolAddress((void**)&h1,  g_h1);
    cudaGetSymbolAddress((void**)&po,  g_po);
    cudaGetSymbolAddress((void**)&pm,  g_pm);
    cudaGetSymbolAddress((void**)&pl,  g_pl);

    dim3 tb(32, 8);

    transpose_k<<<dim3(NTOK / 32, CDIM / 32), tb>>>(x, xl, CDIM, NTOK);
    ln_kernel<<<NTOK, CDIM>>>(xl, ln1_g, ln1_b, xn);
    sgemm_tn<0><<<dim3(768 / 64, NTOK / 64), 256>>>(xn, w_qkv, b_qkv, nullptr,
                                                    qkv, NTOK, 768, CDIM);

    attn_kernel<<<dim3(NTOK / 128, HEADS, NCHUNK), 128>>>(qkv, po, pm, pl);
    attn_combine<<<HEADS * NTOK / 8, 256>>>(po, pm, pl, att);

    sgemm_tn<2><<<dim3(CDIM / 64, NTOK / 64), 256>>>(att, w_proj, b_proj, xl,
                                                     xl, NTOK, CDIM, CDIM);
    ln_kernel<<<NTOK, CDIM>>>(xl, ln2_g, ln2_b, xn);
    sgemm_tn<1><<<dim3(1024 / 64, NTOK / 64), 256>>>(xn, w_mlp1, b_mlp1, nullptr,
                                                     h1, NTOK, 1024, CDIM);
    sgemm_tn<2><<<dim3(CDIM / 64, NTOK / 64), 256>>>(h1, w_mlp2, b_mlp2, xl,
                                                     xl, NTOK, CDIM, 4 * CDIM);
    transpose_k<<<dim3(CDIM / 32, NTOK / 32), tb>>>(xl, out, NTOK, CDIM);
}

// round 4
// speedup vs baseline: 2.1135x; 1.8241x over previous
#include <cuda_runtime.h>
#include <cuda_bf16.h>
#include <math.h>
#include <stdint.h>

// ---------------------------------------------------------------------------
// TransformerBlock: x[1,256,64,64]. N=4096 tokens, C=256, 8 heads, d=32.
// Attention: FA2-style on mma.sync bf16 (hi/lo 3-term = fp32-accurate).
// ---------------------------------------------------------------------------

#define NTOK 4096
#define CDIM 256
#define HEADS 8
#define HDIM 32

__device__ float g_xl[NTOK * CDIM];
__device__ float g_xn[NTOK * CDIM];
__device__ float g_qkv[NTOK * 3 * CDIM];
__device__ float g_att[NTOK * CDIM];
__device__ float g_h1[NTOK * 4 * CDIM];

// ============================ helpers ======================================
__device__ __forceinline__ uint16_t bf16_rn(float x) {
    __nv_bfloat16 h = __float2bfloat16(x);
    return *reinterpret_cast<uint16_t*>(&h);
}
__device__ __forceinline__ float bf16f(uint16_t u) {
    return __uint_as_float((uint32_t)u << 16);
}
__device__ __forceinline__ uint32_t pack2(uint16_t lo, uint16_t hi) {
    return (uint32_t)lo | ((uint32_t)hi << 16);
}
// split (x,y) into packed bf16x2 hi and lo parts (lo = residual)
__device__ __forceinline__ void bfsplit2(float x, float y,
                                         uint32_t& hi, uint32_t& lo) {
    uint16_t hx = bf16_rn(x), hy = bf16_rn(y);
    hi = pack2(hx, hy);
    lo = pack2(bf16_rn(x - bf16f(hx)), bf16_rn(y - bf16f(hy)));
}

#define MMA(c, a, b0, b1)                                                      \
    asm volatile("mma.sync.aligned.m16n8k16.row.col.f32.bf16.bf16.f32 "        \
        "{%0,%1,%2,%3}, {%4,%5,%6,%7}, {%8,%9}, {%0,%1,%2,%3};"                \
        : "+f"((c)[0]), "+f"((c)[1]), "+f"((c)[2]), "+f"((c)[3])               \
        : "r"((a)[0]), "r"((a)[1]), "r"((a)[2]), "r"((a)[3]),                  \
          "r"(b0), "r"(b1))

__device__ __forceinline__ float exp2_fast(float y) {
    y = fmaxf(y, -126.0f);
    int ni = __float2int_rn(y);
    float f = y - (float)ni;
    float p = 1.5403530e-4f;
    p = fmaf(p, f, 1.33335581e-3f);
    p = fmaf(p, f, 9.61812911e-3f);
    p = fmaf(p, f, 5.55041087e-2f);
    p = fmaf(p, f, 2.40226507e-1f);
    p = fmaf(p, f, 6.93147181e-1f);
    p = fmaf(p, f, 1.0f);
    float sc = __int_as_float((ni + 127) << 23);
    return p * sc;
}

// ============================ generic kernels ==============================
__global__ void transpose_k(const float* __restrict__ src, float* __restrict__ dst,
                            int R, int C) {
    __shared__ float tile[32][33];
    int c0 = blockIdx.x * 32, r0 = blockIdx.y * 32;
    int x = threadIdx.x, y = threadIdx.y;
#pragma unroll
    for (int i = y; i < 32; i += 8)
        tile[i][x] = src[(size_t)(r0 + i) * C + c0 + x];
    __syncthreads();
#pragma unroll
    for (int i = y; i < 32; i += 8)
        dst[(size_t)(c0 + i) * R + r0 + x] = tile[x][i];
}

__global__ void ln_kernel(const float* __restrict__ in, const float* __restrict__ g,
                          const float* __restrict__ b, float* __restrict__ out) {
    int n = blockIdx.x;
    int c = threadIdx.x;
    float v = in[n * CDIM + c];
    float s1 = v, s2 = v * v;
#pragma unroll
    for (int off = 16; off > 0; off >>= 1) {
        s1 += __shfl_xor_sync(0xFFFFFFFFu, s1, off);
        s2 += __shfl_xor_sync(0xFFFFFFFFu, s2, off);
    }
    __shared__ float sh1[8], sh2[8];
    int w = c >> 5, lane = c & 31;
    if (lane == 0) { sh1[w] = s1; sh2[w] = s2; }
    __syncthreads();
    float m1 = 0.f, m2 = 0.f;
#pragma unroll
    for (int i = 0; i < 8; i++) { m1 += sh1[i]; m2 += sh2[i]; }
    float mu = m1 * (1.f / CDIM);
    float var = m2 * (1.f / CDIM) - mu * mu;
    float rs = rsqrtf(var + 1e-5f);
    out[n * CDIM + c] = (v - mu) * rs * g[c] + b[c];
}

template <int EPI>
__global__ __launch_bounds__(256)
void sgemm_tn(const float* __restrict__ A, const float* __restrict__ B,
              const float* __restrict__ bias, const float* __restrict__ res,
              float* __restrict__ C, int M, int N, int K) {
    __shared__ float As[16][64];
    __shared__ float Bs[16][64];
    int tid = threadIdx.x;
    int m0 = blockIdx.y * 64, n0 = blockIdx.x * 64;
    int lrow = tid >> 2, lseg = tid & 3;
    int tx = tid & 15, ty = tid >> 4;
    float acc[4][4] = {};

    for (int k0 = 0; k0 < K; k0 += 16) {
        float4 av = *(const float4*)(A + (size_t)(m0 + lrow) * K + k0 + lseg * 4);
        float4 bv = *(const float4*)(B + (size_t)(n0 + lrow) * K + k0 + lseg * 4);
        __syncthreads();
        As[lseg * 4 + 0][lrow] = av.x; As[lseg * 4 + 1][lrow] = av.y;
        As[lseg * 4 + 2][lrow] = av.z; As[lseg * 4 + 3][lrow] = av.w;
        Bs[lseg * 4 + 0][lrow] = bv.x; Bs[lseg * 4 + 1][lrow] = bv.y;
        Bs[lseg * 4 + 2][lrow] = bv.z; Bs[lseg * 4 + 3][lrow] = bv.w;
        __syncthreads();
#pragma unroll
        for (int kk = 0; kk < 16; kk++) {
            float4 a4 = *(const float4*)&As[kk][ty * 4];
            float4 b4 = *(const float4*)&Bs[kk][tx * 4];
            float aa[4] = {a4.x, a4.y, a4.z, a4.w};
            float bb[4] = {b4.x, b4.y, b4.z, b4.w};
#pragma unroll
            for (int i = 0; i < 4; i++)
#pragma unroll
                for (int j = 0; j < 4; j++)
                    acc[i][j] = fmaf(aa[i], bb[j], acc[i][j]);
        }
    }

#pragma unroll
    for (int i = 0; i < 4; i++) {
        int row = m0 + ty * 4 + i;
#pragma unroll
        for (int j = 0; j < 4; j++) {
            int col = n0 + tx * 4 + j;
            float v = acc[i][j] + bias[col];
            if (EPI == 1) v = 0.5f * v * (1.0f + erff(v * 0.70710678118654752f));
            if (EPI == 2) v += res[(size_t)row * N + col];
            C[(size_t)row * N + col] = v;
        }
    }
}

// ============================ mma.sync attention ===========================
// grid (NTOK/128, HEADS), 128 threads (4 warps). Warp w owns queries
// [q0 + 32w, q0 + 32w + 32). KV tiles of 64 keys staged in SMEM as bf16x2
// hi/lo. QK and PV both 3-term bf16 emulation (fp32-level accuracy).
//
// SMEM: Khi/Klo: [key][16 dpairs] stride 17 u32.
//       Vhi/Vlo: [d][32 keypairs] stride 34 u32 (pair = keys 2p,2p+1).
__global__ __launch_bounds__(128)
void attn_mma(const float* __restrict__ qkv, float* __restrict__ att) {
    __shared__ uint32_t Khi[64 * 17], Klo[64 * 17];
    __shared__ uint32_t Vhi[32 * 34], Vlo[32 * 34];

    const int t = threadIdx.x;
    const int w = t >> 5;
    const int lane = t & 31;
    const int g = lane >> 2;          // fragment row group
    const int l2 = lane & 3;          // fragment col group
    const int h = blockIdx.y;
    const int q0 = blockIdx.x * 128;

    // ---- Q fragments (resident whole kernel), scaled by 1/sqrt(d)*log2e ----
    uint32_t qhi[2][2][4], qlo[2][2][4];
    {
        const float qs = 0.17677669529663687f * 1.4426950408889634f;
        const int qrow = q0 + w * 32;
#pragma unroll
        for (int mt = 0; mt < 2; mt++)
#pragma unroll
        for (int ks = 0; ks < 2; ks++) {
            const float* r0p = qkv + (size_t)(qrow + mt * 16 + g) * 768 +
                               h * HDIM + ks * 16 + 2 * l2;
            const float* r1p = r0p + 8 * 768;
            float2 v0 = *(const float2*)r0p;
            float2 v1 = *(const float2*)r1p;
            float2 v2 = *(const float2*)(r0p + 8);
            float2 v3 = *(const float2*)(r1p + 8);
            bfsplit2(v0.x * qs, v0.y * qs, qhi[mt][ks][0], qlo[mt][ks][0]);
            bfsplit2(v1.x * qs, v1.y * qs, qhi[mt][ks][1], qlo[mt][ks][1]);
            bfsplit2(v2.x * qs, v2.y * qs, qhi[mt][ks][2], qlo[mt][ks][2]);
            bfsplit2(v3.x * qs, v3.y * qs, qhi[mt][ks][3], qlo[mt][ks][3]);
        }
    }

    float o[2][4][4];
#pragma unroll
    for (int mt = 0; mt < 2; mt++)
#pragma unroll
        for (int nt = 0; nt < 4; nt++)
#pragma unroll
            for (int i = 0; i < 4; i++) o[mt][nt][i] = 0.f;
    float mrow[2][2] = {{-1e30f, -1e30f}, {-1e30f, -1e30f}};
    float lacc[2][2] = {{0.f, 0.f}, {0.f, 0.f}};

    for (int tile = 0; tile < NTOK / 64; tile++) {
        const int key0 = tile * 64;
        if (tile) __syncthreads();   // previous compute done before restaging

        // ---- stage K: thread -> (key, d-half); pairs along d ----
        {
            int key = t >> 1, dh = t & 1;
            const float* kp = qkv + (size_t)(key0 + key) * 768 + 256 +
                              h * HDIM + dh * 16;
#pragma unroll
            for (int e = 0; e < 4; e++) {
                float4 v = ((const float4*)kp)[e];
                uint32_t hi0, lo0, hi1, lo1;
                bfsplit2(v.x, v.y, hi0, lo0);
                bfsplit2(v.z, v.w, hi1, lo1);
                int idx = key * 17 + dh * 8 + e * 2;
                Khi[idx] = hi0; Khi[idx + 1] = hi1;
                Klo[idx] = lo0; Klo[idx + 1] = lo1;
            }
        }
        // ---- stage V transposed: thread -> (keypair, d-quarter) ----
        {
            int kp2 = t >> 2, dq = t & 3;
            const float* va = qkv + (size_t)(key0 + 2 * kp2) * 768 + 512 +
                              h * HDIM + dq * 8;
            const float* vb = va + 768;
            float4 a0 = ((const float4*)va)[0], a1 = ((const float4*)va)[1];
            float4 b0 = ((const float4*)vb)[0], b1 = ((const float4*)vb)[1];
            float av[8] = {a0.x, a0.y, a0.z, a0.w, a1.x, a1.y, a1.z, a1.w};
            float bv[8] = {b0.x, b0.y, b0.z, b0.w, b1.x, b1.y, b1.z, b1.w};
#pragma unroll
            for (int j = 0; j < 8; j++) {
                int d = dq * 8 + j;
                uint32_t hi, lo;
                bfsplit2(av[j], bv[j], hi, lo);   // lower half = even key
                Vhi[d * 34 + kp2] = hi;
                Vlo[d * 34 + kp2] = lo;
            }
        }
        __syncthreads();

        // ---- per warp: 32 queries x 64 keys ----
#pragma unroll
        for (int mt = 0; mt < 2; mt++) {
            // S = Q K^T (3-term)
            float s[8][4];
#pragma unroll
            for (int nt = 0; nt < 8; nt++) {
                int key = g + nt * 8;
                const uint32_t* kh = &Khi[key * 17];
                const uint32_t* kl = &Klo[key * 17];
                uint32_t bh00 = kh[l2],     bh01 = kh[4 + l2];
                uint32_t bh10 = kh[8 + l2], bh11 = kh[12 + l2];
                uint32_t bl00 = kl[l2],     bl01 = kl[4 + l2];
                uint32_t bl10 = kl[8 + l2], bl11 = kl[12 + l2];
                float c[4] = {0.f, 0.f, 0.f, 0.f};
                MMA(c, qhi[mt][0], bh00, bh01);
                MMA(c, qhi[mt][1], bh10, bh11);
                MMA(c, qhi[mt][0], bl00, bl01);
                MMA(c, qhi[mt][1], bl10, bl11);
                MMA(c, qlo[mt][0], bh00, bh01);
                MMA(c, qlo[mt][1], bh10, bh11);
                s[nt][0] = c[0]; s[nt][1] = c[1]; s[nt][2] = c[2]; s[nt][3] = c[3];
            }

            // online softmax (rows g and g+8 of this m-tile)
            float mx0 = -1e30f, mx1 = -1e30f;
#pragma unroll
            for (int nt = 0; nt < 8; nt++) {
                mx0 = fmaxf(mx0, fmaxf(s[nt][0], s[nt][1]));
                mx1 = fmaxf(mx1, fmaxf(s[nt][2], s[nt][3]));
            }
            mx0 = fmaxf(mx0, __shfl_xor_sync(0xFFFFFFFFu, mx0, 1));
            mx0 = fmaxf(mx0, __shfl_xor_sync(0xFFFFFFFFu, mx0, 2));
            mx1 = fmaxf(mx1, __shfl_xor_sync(0xFFFFFFFFu, mx1, 1));
            mx1 = fmaxf(mx1, __shfl_xor_sync(0xFFFFFFFFu, mx1, 2));
            float mn0 = fmaxf(mrow[mt][0], mx0);
            float mn1 = fmaxf(mrow[mt][1], mx1);
            float cr0 = exp2_fast(mrow[mt][0] - mn0);
            float cr1 = exp2_fast(mrow[mt][1] - mn1);
            mrow[mt][0] = mn0; mrow[mt][1] = mn1;
            lacc[mt][0] *= cr0; lacc[mt][1] *= cr1;
#pragma unroll
            for (int nt4 = 0; nt4 < 4; nt4++) {
                o[mt][nt4][0] *= cr0; o[mt][nt4][1] *= cr0;
                o[mt][nt4][2] *= cr1; o[mt][nt4][3] *= cr1;
            }

            // P = exp2(S - m), packed thread-locally into PV A-fragments
            uint32_t phi[4][4], plo[4][4];
            float s0 = 0.f, s1 = 0.f;
#pragma unroll
            for (int nt = 0; nt < 8; nt++) {
                float p0 = exp2_fast(s[nt][0] - mn0);
                float p1 = exp2_fast(s[nt][1] - mn0);
                float p2 = exp2_fast(s[nt][2] - mn1);
                float p3 = exp2_fast(s[nt][3] - mn1);
                s0 += p0 + p1; s1 += p2 + p3;
                int kv = nt >> 1, hf = (nt & 1) * 2;
                uint16_t h0 = bf16_rn(p0), h1 = bf16_rn(p1);
                uint16_t h2 = bf16_rn(p2), h3 = bf16_rn(p3);
                phi[kv][hf]     = pack2(h0, h1);
                phi[kv][hf + 1] = pack2(h2, h3);
                plo[kv][hf]     = pack2(bf16_rn(p0 - bf16f(h0)),
                                        bf16_rn(p1 - bf16f(h1)));
                plo[kv][hf + 1] = pack2(bf16_rn(p2 - bf16f(h2)),
                                        bf16_rn(p3 - bf16f(h3)));
            }
            lacc[mt][0] += s0; lacc[mt][1] += s1;

            // O += P V (3-term)
#pragma unroll
            for (int nt4 = 0; nt4 < 4; nt4++) {
                int n = g + nt4 * 8;
                const uint32_t* vh = &Vhi[n * 34];
                const uint32_t* vl = &Vlo[n * 34];
#pragma unroll
                for (int kv = 0; kv < 4; kv++) {
                    uint32_t vh0 = vh[kv * 8 + l2], vh1 = vh[kv * 8 + 4 + l2];
                    uint32_t vl0 = vl[kv * 8 + l2], vl1 = vl[kv * 8 + 4 + l2];
                    MMA(o[mt][nt4], phi[kv], vh0, vh1);
                    MMA(o[mt][nt4], phi[kv], vl0, vl1);
                    MMA(o[mt][nt4], plo[kv], vh0, vh1);
                }
            }
        }
    }

    // ---- normalize + write ----
#pragma unroll
    for (int mt = 0; mt < 2; mt++) {
        float l0 = lacc[mt][0];
        l0 += __shfl_xor_sync(0xFFFFFFFFu, l0, 1);
        l0 += __shfl_xor_sync(0xFFFFFFFFu, l0, 2);
        float l1 = lacc[mt][1];
        l1 += __shfl_xor_sync(0xFFFFFFFFu, l1, 1);
        l1 += __shfl_xor_sync(0xFFFFFFFFu, l1, 2);
        float i0 = 1.0f / l0, i1 = 1.0f / l1;
        int r0 = q0 + w * 32 + mt * 16 + g;
        float* p0 = att + (size_t)r0 * CDIM + h * HDIM + 2 * l2;
        float* p1 = p0 + 8 * CDIM;
#pragma unroll
        for (int nt4 = 0; nt4 < 4; nt4++) {
            *(float2*)(p0 + nt4 * 8) =
                make_float2(o[mt][nt4][0] * i0, o[mt][nt4][1] * i0);
            *(float2*)(p1 + nt4 * 8) =
                make_float2(o[mt][nt4][2] * i1, o[mt][nt4][3] * i1);
        }
    }
}

// ============================ launch =======================================
extern "C" void kernel_launch(void* const* d_in, const int* in_sizes, int n_in,
                              void* d_out, int out_size) {
    const float* x      = (const float*)d_in[0];
    const float* ln1_g  = (const float*)d_in[1];
    const float* ln1_b  = (const float*)d_in[2];
    const float* w_qkv  = (const float*)d_in[3];
    const float* b_qkv  = (const float*)d_in[4];
    const float* w_proj = (const float*)d_in[5];
    const float* b_proj = (const float*)d_in[6];
    const float* ln2_g  = (const float*)d_in[7];
    const float* ln2_b  = (const float*)d_in[8];
    const float* w_mlp1 = (const float*)d_in[9];
    const float* b_mlp1 = (const float*)d_in[10];
    const float* w_mlp2 = (const float*)d_in[11];
    const float* b_mlp2 = (const float*)d_in[12];
    float* out = (float*)d_out;

    float *xl, *xn, *qkv, *att, *h1;
    cudaGetSymbolAddress((void**)&xl,  g_xl);
    cudaGetSymbolAddress((void**)&xn,  g_xn);
    cudaGetSymbolAddress((void**)&qkv, g_qkv);
    cudaGetSymbolAddress((void**)&att, g_att);
    cudaGetSymbolAddress((void**)&h1,  g_h1);

    dim3 tb(32, 8);

    transpose_k<<<dim3(NTOK / 32, CDIM / 32), tb>>>(x, xl, CDIM, NTOK);
    ln_kernel<<<NTOK, CDIM>>>(xl, ln1_g, ln1_b, xn);
    sgemm_tn<0><<<dim3(768 / 64, NTOK / 64), 256>>>(xn, w_qkv, b_qkv, nullptr,
                                                    qkv, NTOK, 768, CDIM);

    attn_mma<<<dim3(NTOK / 128, HEADS), 128>>>(qkv, att);

    sgemm_tn<2><<<dim3(CDIM / 64, NTOK / 64), 256>>>(att, w_proj, b_proj, xl,
                                                     xl, NTOK, CDIM, CDIM);
    ln_kernel<<<NTOK, CDIM>>>(xl, ln2_g, ln2_b, xn);
    sgemm_tn<1><<<dim3(1024 / 64, NTOK / 64), 256>>>(xn, w_mlp1, b_mlp1, nullptr,
                                                     h1, NTOK, 1024, CDIM);
    sgemm_tn<2><<<dim3(CDIM / 64, NTOK / 64), 256>>>(h1, w_mlp2, b_mlp2, xl,
                                                     xl, NTOK, CDIM, 4 * CDIM);
    transpose_k<<<dim3(CDIM / 32, NTOK / 32), tb>>>(xl, out, NTOK, CDIM);
}

// round 5
// speedup vs baseline: 2.4902x; 1.1782x over previous
#include <cuda_runtime.h>
#include <cuda_bf16.h>
#include <math.h>
#include <stdint.h>

// ---------------------------------------------------------------------------
// TransformerBlock: x[1,256,64,64]. N=4096 tokens, C=256, 8 heads, d=32.
// Attention + all GEMMs on mma.sync bf16 3-term (fp32-accurate).
// ---------------------------------------------------------------------------

#define NTOK 4096
#define CDIM 256
#define HEADS 8
#define HDIM 32

__device__ float g_xl[NTOK * CDIM];
__device__ float g_qkv[NTOK * 3 * CDIM];
__device__ __nv_bfloat16 g_xn_hi[NTOK * CDIM],  g_xn_lo[NTOK * CDIM];
__device__ __nv_bfloat16 g_att_hi[NTOK * CDIM], g_att_lo[NTOK * CDIM];
__device__ __nv_bfloat16 g_h1_hi[NTOK * 4 * CDIM], g_h1_lo[NTOK * 4 * CDIM];
// split weights: qkv @0, proj @196608, mlp1 @262144, mlp2 @524288
#define WOFF_QKV  0
#define WOFF_PROJ 196608
#define WOFF_MLP1 262144
#define WOFF_MLP2 524288
__device__ __nv_bfloat16 g_w_hi[786432], g_w_lo[786432];

// ============================ helpers ======================================
__device__ __forceinline__ uint16_t bf16_rn(float x) {
    __nv_bfloat16 h = __float2bfloat16(x);
    return *reinterpret_cast<uint16_t*>(&h);
}
__device__ __forceinline__ float bf16f(uint16_t u) {
    return __uint_as_float((uint32_t)u << 16);
}
__device__ __forceinline__ uint32_t pack2(uint16_t lo, uint16_t hi) {
    return (uint32_t)lo | ((uint32_t)hi << 16);
}
__device__ __forceinline__ void bfsplit2(float x, float y,
                                         uint32_t& hi, uint32_t& lo) {
    uint16_t hx = bf16_rn(x), hy = bf16_rn(y);
    hi = pack2(hx, hy);
    lo = pack2(bf16_rn(x - bf16f(hx)), bf16_rn(y - bf16f(hy)));
}

#define MMA(c, a, b0, b1)                                                      \
    asm volatile("mma.sync.aligned.m16n8k16.row.col.f32.bf16.bf16.f32 "        \
        "{%0,%1,%2,%3}, {%4,%5,%6,%7}, {%8,%9}, {%0,%1,%2,%3};"                \
        : "+f"((c)[0]), "+f"((c)[1]), "+f"((c)[2]), "+f"((c)[3])               \
        : "r"((a)[0]), "r"((a)[1]), "r"((a)[2]), "r"((a)[3]),                  \
          "r"(b0), "r"(b1))

__device__ __forceinline__ float exp2_fast(float y) {
    y = fmaxf(y, -126.0f);
    int ni = __float2int_rn(y);
    float f = y - (float)ni;
    float p = 1.5403530e-4f;
    p = fmaf(p, f, 1.33335581e-3f);
    p = fmaf(p, f, 9.61812911e-3f);
    p = fmaf(p, f, 5.55041087e-2f);
    p = fmaf(p, f, 2.40226507e-1f);
    p = fmaf(p, f, 6.93147181e-1f);
    p = fmaf(p, f, 1.0f);
    float sc = __int_as_float((ni + 127) << 23);
    return p * sc;
}

// ============================ small kernels ================================
__global__ void transpose_k(const float* __restrict__ src, float* __restrict__ dst,
                            int R, int C) {
    __shared__ float tile[32][33];
    int c0 = blockIdx.x * 32, r0 = blockIdx.y * 32;
    int x = threadIdx.x, y = threadIdx.y;
#pragma unroll
    for (int i = y; i < 32; i += 8)
        tile[i][x] = src[(size_t)(r0 + i) * C + c0 + x];
    __syncthreads();
#pragma unroll
    for (int i = y; i < 32; i += 8)
        dst[(size_t)(c0 + i) * R + r0 + x] = tile[x][i];
}

// split fp32 -> bf16 hi/lo
__global__ void wsplit_k(const float* __restrict__ src,
                         __nv_bfloat16* __restrict__ hi,
                         __nv_bfloat16* __restrict__ lo, int n) {
    int i = blockIdx.x * 256 + threadIdx.x;
    if (i < n) {
        float v = src[i];
        __nv_bfloat16 h = __float2bfloat16(v);
        hi[i] = h;
        lo[i] = __float2bfloat16(v - __bfloat162float(h));
    }
}

// LayerNorm writing bf16 hi/lo
__global__ void ln_kernel(const float* __restrict__ in, const float* __restrict__ g,
                          const float* __restrict__ b,
                          __nv_bfloat16* __restrict__ ohi,
                          __nv_bfloat16* __restrict__ olo) {
    int n = blockIdx.x;
    int c = threadIdx.x;
    float v = in[n * CDIM + c];
    float s1 = v, s2 = v * v;
#pragma unroll
    for (int off = 16; off > 0; off >>= 1) {
        s1 += __shfl_xor_sync(0xFFFFFFFFu, s1, off);
        s2 += __shfl_xor_sync(0xFFFFFFFFu, s2, off);
    }
    __shared__ float sh1[8], sh2[8];
    int w = c >> 5, lane = c & 31;
    if (lane == 0) { sh1[w] = s1; sh2[w] = s2; }
    __syncthreads();
    float m1 = 0.f, m2 = 0.f;
#pragma unroll
    for (int i = 0; i < 8; i++) { m1 += sh1[i]; m2 += sh2[i]; }
    float mu = m1 * (1.f / CDIM);
    float var = m2 * (1.f / CDIM) - mu * mu;
    float rs = rsqrtf(var + 1e-5f);
    float y = (v - mu) * rs * g[c] + b[c];
    __nv_bfloat16 h = __float2bfloat16(y);
    ohi[n * CDIM + c] = h;
    olo[n * CDIM + c] = __float2bfloat16(y - __bfloat162float(h));
}

// ============================ bf16 3-term GEMM =============================
// C[M,N] = A[M,K] * B[N,K]^T + bias. A,B pre-split bf16 hi/lo.
// EPI: 0 = write fp32 C; 1 = GELU, write bf16 hi/lo; 2 = +res, write fp32.
// BM=128, BN=64, BK=32; 128 threads = 4 warps (2x2), warp tile 64x32.
template <int EPI>
__global__ __launch_bounds__(128)
void hgemm_tn(const __nv_bfloat16* __restrict__ Ah, const __nv_bfloat16* __restrict__ Al,
              const __nv_bfloat16* __restrict__ Bh, const __nv_bfloat16* __restrict__ Bl,
              const float* __restrict__ bias, const float* __restrict__ res,
              float* __restrict__ Cf,
              __nv_bfloat16* __restrict__ Ch, __nv_bfloat16* __restrict__ Cl,
              int M, int N, int K) {
    __shared__ uint32_t Ash[128 * 20], Asl[128 * 20];
    __shared__ uint32_t Bsh[64 * 20],  Bsl[64 * 20];

    const int tid = threadIdx.x;
    const int w = tid >> 5, lane = tid & 31;
    const int g = lane >> 2, l2 = lane & 3;
    const int m0 = blockIdx.y * 128, n0 = blockIdx.x * 64;
    const int mw = (w >> 1) * 64, nw = (w & 1) * 32;
    const int Ku = K >> 1;

    const uint32_t* A32h = (const uint32_t*)Ah;
    const uint32_t* A32l = (const uint32_t*)Al;
    const uint32_t* B32h = (const uint32_t*)Bh;
    const uint32_t* B32l = (const uint32_t*)Bl;

    float acc[4][4][4] = {};

    for (int k0 = 0; k0 < K; k0 += 32) {
        if (k0) __syncthreads();
        {   // stage A: row = tid, 16 u32 per row per array
            int row = tid;
            const uint4* pH = (const uint4*)(A32h + (size_t)(m0 + row) * Ku + (k0 >> 1));
            const uint4* pL = (const uint4*)(A32l + (size_t)(m0 + row) * Ku + (k0 >> 1));
            uint4* dH = (uint4*)&Ash[row * 20];
            uint4* dL = (uint4*)&Asl[row * 20];
#pragma unroll
            for (int e = 0; e < 4; e++) { dH[e] = pH[e]; dL[e] = pL[e]; }
        }
        {   // stage B: row = tid>>1, half = tid&1 (8 u32)
            int row = tid >> 1, hf = tid & 1;
            const uint4* pH = (const uint4*)(B32h + (size_t)(n0 + row) * Ku + (k0 >> 1) + hf * 8);
            const uint4* pL = (const uint4*)(B32l + (size_t)(n0 + row) * Ku + (k0 >> 1) + hf * 8);
            uint4* dH = (uint4*)&Bsh[row * 20 + hf * 8];
            uint4* dL = (uint4*)&Bsl[row * 20 + hf * 8];
#pragma unroll
            for (int e = 0; e < 2; e++) { dH[e] = pH[e]; dL[e] = pL[e]; }
        }
        __syncthreads();

#pragma unroll
        for (int ks = 0; ks < 2; ks++) {
            uint32_t ah[4][4], al[4][4], bh[4][2], bl[4][2];
#pragma unroll
            for (int mt = 0; mt < 4; mt++) {
                int r0 = (mw + mt * 16 + g) * 20 + ks * 8;
                int r1 = (mw + mt * 16 + 8 + g) * 20 + ks * 8;
                ah[mt][0] = Ash[r0 + l2];     ah[mt][1] = Ash[r1 + l2];
                ah[mt][2] = Ash[r0 + 4 + l2]; ah[mt][3] = Ash[r1 + 4 + l2];
                al[mt][0] = Asl[r0 + l2];     al[mt][1] = Asl[r1 + l2];
                al[mt][2] = Asl[r0 + 4 + l2]; al[mt][3] = Asl[r1 + 4 + l2];
            }
#pragma unroll
            for (int nt = 0; nt < 4; nt++) {
                int rb = (nw + nt * 8 + g) * 20 + ks * 8;
                bh[nt][0] = Bsh[rb + l2]; bh[nt][1] = Bsh[rb + 4 + l2];
                bl[nt][0] = Bsl[rb + l2]; bl[nt][1] = Bsl[rb + 4 + l2];
            }
#pragma unroll
            for (int mt = 0; mt < 4; mt++)
#pragma unroll
                for (int nt = 0; nt < 4; nt++) {
                    MMA(acc[mt][nt], ah[mt], bh[nt][0], bh[nt][1]);
                    MMA(acc[mt][nt], ah[mt], bl[nt][0], bl[nt][1]);
                    MMA(acc[mt][nt], al[mt], bh[nt][0], bh[nt][1]);
                }
        }
    }

    // ---- epilogue ----
#pragma unroll
    for (int mt = 0; mt < 4; mt++)
#pragma unroll
        for (int nt = 0; nt < 4; nt++) {
            int row = m0 + mw + mt * 16 + g;
            int col = n0 + nw + nt * 8 + 2 * l2;
            float b0 = bias[col], b1 = bias[col + 1];
            float v0 = acc[mt][nt][0] + b0, v1 = acc[mt][nt][1] + b1;
            float v2 = acc[mt][nt][2] + b0, v3 = acc[mt][nt][3] + b1;
            if (EPI == 1) {
                v0 = 0.5f * v0 * (1.0f + erff(v0 * 0.70710678118654752f));
                v1 = 0.5f * v1 * (1.0f + erff(v1 * 0.70710678118654752f));
                v2 = 0.5f * v2 * (1.0f + erff(v2 * 0.70710678118654752f));
                v3 = 0.5f * v3 * (1.0f + erff(v3 * 0.70710678118654752f));
                uint32_t hi, lo;
                bfsplit2(v0, v1, hi, lo);
                ((uint32_t*)Ch)[((size_t)row * N + col) >> 1] = hi;
                ((uint32_t*)Cl)[((size_t)row * N + col) >> 1] = lo;
                bfsplit2(v2, v3, hi, lo);
                ((uint32_t*)Ch)[((size_t)(row + 8) * N + col) >> 1] = hi;
                ((uint32_t*)Cl)[((size_t)(row + 8) * N + col) >> 1] = lo;
            } else {
                if (EPI == 2) {
                    const float2 r0 = *(const float2*)(res + (size_t)row * N + col);
                    const float2 r1 = *(const float2*)(res + (size_t)(row + 8) * N + col);
                    v0 += r0.x; v1 += r0.y; v2 += r1.x; v3 += r1.y;
                }
                *(float2*)(Cf + (size_t)row * N + col) = make_float2(v0, v1);
                *(float2*)(Cf + (size_t)(row + 8) * N + col) = make_float2(v2, v3);
            }
        }
}

// ============================ mma.sync attention ===========================
__global__ __launch_bounds__(128)
void attn_mma(const float* __restrict__ qkv,
              __nv_bfloat16* __restrict__ att_hi,
              __nv_bfloat16* __restrict__ att_lo) {
    __shared__ uint32_t Khi[64 * 17], Klo[64 * 17];
    __shared__ uint32_t Vhi[32 * 34], Vlo[32 * 34];

    const int t = threadIdx.x;
    const int w = t >> 5;
    const int lane = t & 31;
    const int g = lane >> 2;
    const int l2 = lane & 3;
    const int h = blockIdx.y;
    const int q0 = blockIdx.x * 128;

    uint32_t qhi[2][2][4], qlo[2][2][4];
    {
        const float qs = 0.17677669529663687f * 1.4426950408889634f;
        const int qrow = q0 + w * 32;
#pragma unroll
        for (int mt = 0; mt < 2; mt++)
#pragma unroll
        for (int ks = 0; ks < 2; ks++) {
            const float* r0p = qkv + (size_t)(qrow + mt * 16 + g) * 768 +
                               h * HDIM + ks * 16 + 2 * l2;
            const float* r1p = r0p + 8 * 768;
            float2 v0 = *(const float2*)r0p;
            float2 v1 = *(const float2*)r1p;
            float2 v2 = *(const float2*)(r0p + 8);
            float2 v3 = *(const float2*)(r1p + 8);
            bfsplit2(v0.x * qs, v0.y * qs, qhi[mt][ks][0], qlo[mt][ks][0]);
            bfsplit2(v1.x * qs, v1.y * qs, qhi[mt][ks][1], qlo[mt][ks][1]);
            bfsplit2(v2.x * qs, v2.y * qs, qhi[mt][ks][2], qlo[mt][ks][2]);
            bfsplit2(v3.x * qs, v3.y * qs, qhi[mt][ks][3], qlo[mt][ks][3]);
        }
    }

    float o[2][4][4];
#pragma unroll
    for (int mt = 0; mt < 2; mt++)
#pragma unroll
        for (int nt = 0; nt < 4; nt++)
#pragma unroll
            for (int i = 0; i < 4; i++) o[mt][nt][i] = 0.f;
    float mrow[2][2] = {{-1e30f, -1e30f}, {-1e30f, -1e30f}};
    float lacc[2][2] = {{0.f, 0.f}, {0.f, 0.f}};

    for (int tile = 0; tile < NTOK / 64; tile++) {
        const int key0 = tile * 64;
        if (tile) __syncthreads();

        {
            int key = t >> 1, dh = t & 1;
            const float* kp = qkv + (size_t)(key0 + key) * 768 + 256 +
                              h * HDIM + dh * 16;
#pragma unroll
            for (int e = 0; e < 4; e++) {
                float4 v = ((const float4*)kp)[e];
                uint32_t hi0, lo0, hi1, lo1;
                bfsplit2(v.x, v.y, hi0, lo0);
                bfsplit2(v.z, v.w, hi1, lo1);
                int idx = key * 17 + dh * 8 + e * 2;
                Khi[idx] = hi0; Khi[idx + 1] = hi1;
                Klo[idx] = lo0; Klo[idx + 1] = lo1;
            }
        }
        {
            int kp2 = t >> 2, dq = t & 3;
            const float* va = qkv + (size_t)(key0 + 2 * kp2) * 768 + 512 +
                              h * HDIM + dq * 8;
            const float* vb = va + 768;
            float4 a0 = ((const float4*)va)[0], a1 = ((const float4*)va)[1];
            float4 b0 = ((const float4*)vb)[0], b1 = ((const float4*)vb)[1];
            float av[8] = {a0.x, a0.y, a0.z, a0.w, a1.x, a1.y, a1.z, a1.w};
            float bv[8] = {b0.x, b0.y, b0.z, b0.w, b1.x, b1.y, b1.z, b1.w};
#pragma unroll
            for (int j = 0; j < 8; j++) {
                int d = dq * 8 + j;
                uint32_t hi, lo;
                bfsplit2(av[j], bv[j], hi, lo);
                Vhi[d * 34 + kp2] = hi;
                Vlo[d * 34 + kp2] = lo;
            }
        }
        __syncthreads();

#pragma unroll
        for (int mt = 0; mt < 2; mt++) {
            float s[8][4];
#pragma unroll
            for (int nt = 0; nt < 8; nt++) {
                int key = g + nt * 8;
                const uint32_t* kh = &Khi[key * 17];
                const uint32_t* kl = &Klo[key * 17];
                uint32_t bh00 = kh[l2],     bh01 = kh[4 + l2];
                uint32_t bh10 = kh[8 + l2], bh11 = kh[12 + l2];
                uint32_t bl00 = kl[l2],     bl01 = kl[4 + l2];
                uint32_t bl10 = kl[8 + l2], bl11 = kl[12 + l2];
                float c[4] = {0.f, 0.f, 0.f, 0.f};
                MMA(c, qhi[mt][0], bh00, bh01);
                MMA(c, qhi[mt][1], bh10, bh11);
                MMA(c, qhi[mt][0], bl00, bl01);
                MMA(c, qhi[mt][1], bl10, bl11);
                MMA(c, qlo[mt][0], bh00, bh01);
                MMA(c, qlo[mt][1], bh10, bh11);
                s[nt][0] = c[0]; s[nt][1] = c[1]; s[nt][2] = c[2]; s[nt][3] = c[3];
            }

            float mx0 = -1e30f, mx1 = -1e30f;
#pragma unroll
            for (int nt = 0; nt < 8; nt++) {
                mx0 = fmaxf(mx0, fmaxf(s[nt][0], s[nt][1]));
                mx1 = fmaxf(mx1, fmaxf(s[nt][2], s[nt][3]));
            }
            mx0 = fmaxf(mx0, __shfl_xor_sync(0xFFFFFFFFu, mx0, 1));
            mx0 = fmaxf(mx0, __shfl_xor_sync(0xFFFFFFFFu, mx0, 2));
            mx1 = fmaxf(mx1, __shfl_xor_sync(0xFFFFFFFFu, mx1, 1));
            mx1 = fmaxf(mx1, __shfl_xor_sync(0xFFFFFFFFu, mx1, 2));
            float mn0 = fmaxf(mrow[mt][0], mx0);
            float mn1 = fmaxf(mrow[mt][1], mx1);
            float cr0 = exp2_fast(mrow[mt][0] - mn0);
            float cr1 = exp2_fast(mrow[mt][1] - mn1);
            mrow[mt][0] = mn0; mrow[mt][1] = mn1;
            lacc[mt][0] *= cr0; lacc[mt][1] *= cr1;
#pragma unroll
            for (int nt4 = 0; nt4 < 4; nt4++) {
                o[mt][nt4][0] *= cr0; o[mt][nt4][1] *= cr0;
                o[mt][nt4][2] *= cr1; o[mt][nt4][3] *= cr1;
            }

            uint32_t phi[4][4], plo[4][4];
            float s0 = 0.f, s1 = 0.f;
#pragma unroll
            for (int nt = 0; nt < 8; nt++) {
                float p0 = exp2_fast(s[nt][0] - mn0);
                float p1 = exp2_fast(s[nt][1] - mn0);
                float p2 = exp2_fast(s[nt][2] - mn1);
                float p3 = exp2_fast(s[nt][3] - mn1);
                s0 += p0 + p1; s1 += p2 + p3;
                int kv = nt >> 1, hf = (nt & 1) * 2;
                uint16_t h0 = bf16_rn(p0), h1 = bf16_rn(p1);
                uint16_t h2 = bf16_rn(p2), h3 = bf16_rn(p3);
                phi[kv][hf]     = pack2(h0, h1);
                phi[kv][hf + 1] = pack2(h2, h3);
                plo[kv][hf]     = pack2(bf16_rn(p0 - bf16f(h0)),
                                        bf16_rn(p1 - bf16f(h1)));
                plo[kv][hf + 1] = pack2(bf16_rn(p2 - bf16f(h2)),
                                        bf16_rn(p3 - bf16f(h3)));
            }
            lacc[mt][0] += s0; lacc[mt][1] += s1;

#pragma unroll
            for (int nt4 = 0; nt4 < 4; nt4++) {
                int n = g + nt4 * 8;
                const uint32_t* vh = &Vhi[n * 34];
                const uint32_t* vl = &Vlo[n * 34];
#pragma unroll
                for (int kv = 0; kv < 4; kv++) {
                    uint32_t vh0 = vh[kv * 8 + l2], vh1 = vh[kv * 8 + 4 + l2];
                    uint32_t vl0 = vl[kv * 8 + l2], vl1 = vl[kv * 8 + 4 + l2];
                    MMA(o[mt][nt4], phi[kv], vh0, vh1);
                    MMA(o[mt][nt4], phi[kv], vl0, vl1);
                    MMA(o[mt][nt4], plo[kv], vh0, vh1);
                }
            }
        }
    }

    // ---- normalize + write bf16 hi/lo ----
#pragma unroll
    for (int mt = 0; mt < 2; mt++) {
        float l0 = lacc[mt][0];
        l0 += __shfl_xor_sync(0xFFFFFFFFu, l0, 1);
        l0 += __shfl_xor_sync(0xFFFFFFFFu, l0, 2);
        float l1 = lacc[mt][1];
        l1 += __shfl_xor_sync(0xFFFFFFFFu, l1, 1);
        l1 += __shfl_xor_sync(0xFFFFFFFFu, l1, 2);
        float i0 = 1.0f / l0, i1 = 1.0f / l1;
        int r0 = q0 + w * 32 + mt * 16 + g;
#pragma unroll
        for (int nt4 = 0; nt4 < 4; nt4++) {
            int col = h * HDIM + nt4 * 8 + 2 * l2;
            uint32_t hi, lo;
            bfsplit2(o[mt][nt4][0] * i0, o[mt][nt4][1] * i0, hi, lo);
            ((uint32_t*)att_hi)[((size_t)r0 * CDIM + col) >> 1] = hi;
            ((uint32_t*)att_lo)[((size_t)r0 * CDIM + col) >> 1] = lo;
            bfsplit2(o[mt][nt4][2] * i1, o[mt][nt4][3] * i1, hi, lo);
            ((uint32_t*)att_hi)[((size_t)(r0 + 8) * CDIM + col) >> 1] = hi;
            ((uint32_t*)att_lo)[((size_t)(r0 + 8) * CDIM + col) >> 1] = lo;
        }
    }
}

// ============================ launch =======================================
extern "C" void kernel_launch(void* const* d_in, const int* in_sizes, int n_in,
                              void* d_out, int out_size) {
    const float* x      = (const float*)d_in[0];
    const float* ln1_g  = (const float*)d_in[1];
    const float* ln1_b  = (const float*)d_in[2];
    const float* w_qkv  = (const float*)d_in[3];
    const float* b_qkv  = (const float*)d_in[4];
    const float* w_proj = (const float*)d_in[5];
    const float* b_proj = (const float*)d_in[6];
    const float* ln2_g  = (const float*)d_in[7];
    const float* ln2_b  = (const float*)d_in[8];
    const float* w_mlp1 = (const float*)d_in[9];
    const float* b_mlp1 = (const float*)d_in[10];
    const float* w_mlp2 = (const float*)d_in[11];
    const float* b_mlp2 = (const float*)d_in[12];
    float* out = (float*)d_out;

    float *xl, *qkv;
    __nv_bfloat16 *xnh, *xnl, *atth, *attl, *h1h, *h1l, *wh, *wl;
    cudaGetSymbolAddress((void**)&xl,   g_xl);
    cudaGetSymbolAddress((void**)&qkv,  g_qkv);
    cudaGetSymbolAddress((void**)&xnh,  g_xn_hi);
    cudaGetSymbolAddress((void**)&xnl,  g_xn_lo);
    cudaGetSymbolAddress((void**)&atth, g_att_hi);
    cudaGetSymbolAddress((void**)&attl, g_att_lo);
    cudaGetSymbolAddress((void**)&h1h,  g_h1_hi);
    cudaGetSymbolAddress((void**)&h1l,  g_h1_lo);
    cudaGetSymbolAddress((void**)&wh,   g_w_hi);
    cudaGetSymbolAddress((void**)&wl,   g_w_lo);

    dim3 tb(32, 8);

    // weight splits (independent of data path)
    wsplit_k<<<(768 * 256 + 255) / 256, 256>>>(w_qkv,  wh + WOFF_QKV,  wl + WOFF_QKV,  768 * 256);
    wsplit_k<<<(256 * 256 + 255) / 256, 256>>>(w_proj, wh + WOFF_PROJ, wl + WOFF_PROJ, 256 * 256);
    wsplit_k<<<(1024 * 256 + 255) / 256, 256>>>(w_mlp1, wh + WOFF_MLP1, wl + WOFF_MLP1, 1024 * 256);
    wsplit_k<<<(256 * 1024 + 255) / 256, 256>>>(w_mlp2, wh + WOFF_MLP2, wl + WOFF_MLP2, 256 * 1024);

    transpose_k<<<dim3(NTOK / 32, CDIM / 32), tb>>>(x, xl, CDIM, NTOK);
    ln_kernel<<<NTOK, CDIM>>>(xl, ln1_g, ln1_b, xnh, xnl);

    // QKV: [4096,768] fp32
    hgemm_tn<0><<<dim3(768 / 64, NTOK / 128), 128>>>(
        xnh, xnl, wh + WOFF_QKV, wl + WOFF_QKV, b_qkv, nullptr,
        qkv, nullptr, nullptr, NTOK, 768, CDIM);

    attn_mma<<<dim3(NTOK / 128, HEADS), 128>>>(qkv, atth, attl);

    // proj + residual
    hgemm_tn<2><<<dim3(CDIM / 64, NTOK / 128), 128>>>(
        atth, attl, wh + WOFF_PROJ, wl + WOFF_PROJ, b_proj, xl,
        xl, nullptr, nullptr, NTOK, CDIM, CDIM);

    ln_kernel<<<NTOK, CDIM>>>(xl, ln2_g, ln2_b, xnh, xnl);

    // MLP1 + GELU -> bf16 hi/lo
    hgemm_tn<1><<<dim3(1024 / 64, NTOK / 128), 128>>>(
        xnh, xnl, wh + WOFF_MLP1, wl + WOFF_MLP1, b_mlp1, nullptr,
        nullptr, h1h, h1l, NTOK, 1024, CDIM);

    // MLP2 + residual
    hgemm_tn<2><<<dim3(CDIM / 64, NTOK / 128), 128>>>(
        h1h, h1l, wh + WOFF_MLP2, wl + WOFF_MLP2, b_mlp2, xl,
        xl, nullptr, nullptr, NTOK, CDIM, 4 * CDIM);

    transpose_k<<<dim3(CDIM / 32, NTOK / 32), tb>>>(xl, out, NTOK, CDIM);
}